// round 1
// baseline (speedup 1.0000x reference)
#include <cuda_runtime.h>
#include <math.h>

// Problem constants
#define PB  128   // batch
#define PH  100   // history length
#define PC  32    // candidates
#define PK  4     // channels
#define PD  400   // dim
#define PE  200   // att dim
#define PCW 100   // channel weight dim
#define PN  (PB*PC)

// Scratch: per-(b,k) attended history u and its projection through W_lin[0:400]
__device__ float u_g[PB*PK*PD];    // 512*400
__device__ float uW_g[PB*PK*PE];   // 512*200

// -----------------------------------------------------------------------------
// Kernel A: one block per (b,k).
//  z[h,e] = sum_d his[b,h,k,d] * W_att[k,d,e]        (100x200x400 GEMM)
//  s[h]   = sum_e q_att[k,e] * tanh(z[h,e] + b_att[k,e])
//  a      = softmax_h(s)
//  u[d]   = sum_h a[h] * his[b,h,k,d]
//  uW[e]  = b_lin[e] + sum_d u[d] * W_lin[d,e]
// GEMM: 256 threads as 16(e) x 16(h), 7x7 register tile, e in 2 chunks (112,88),
// d in tiles of 40 staged through shared memory.
// -----------------------------------------------------------------------------
__global__ __launch_bounds__(256) void kernelA(
    const float* __restrict__ his,
    const float* __restrict__ W_att, const float* __restrict__ b_att,
    const float* __restrict__ q_att, const float* __restrict__ W_lin,
    const float* __restrict__ b_lin)
{
    const int bk = blockIdx.x;
    const int b  = bk >> 2;
    const int k  = bk & 3;
    const int tid = threadIdx.x;
    const int tx = tid & 15;    // e direction
    const int ty = tid >> 4;    // h direction

    __shared__ float his_s[112*41];   // [112 rows][40+1 pad]
    __shared__ float W_s[40*113];     // [40 d][112+1 pad e]
    __shared__ float s_s[112];
    __shared__ float u_s[PD];
    __shared__ float red_s[2];

    // init
    for (int i = tid; i < 112; i += 256) s_s[i] = 0.f;
    for (int i = tid; i < 12*41; i += 256) his_s[100*41 + i] = 0.f; // pad rows 100..111
    __syncthreads();

    const float* hisB = his + ((size_t)b*PH)*(PK*PD) + (size_t)k*PD;  // hisB[h*(K*D)+d]

    for (int chunk = 0; chunk < 2; ++chunk) {
        const int e0 = chunk * 112;
        const int cwid = (chunk == 0) ? 112 : 88;

        float acc[7][7];
        #pragma unroll
        for (int i = 0; i < 7; ++i)
            #pragma unroll
            for (int j = 0; j < 7; ++j) acc[i][j] = 0.f;

        // zero W_s so padded e-columns contribute 0
        for (int i = tid; i < 40*113; i += 256) W_s[i] = 0.f;
        __syncthreads();

        for (int dt = 0; dt < 10; ++dt) {
            const int d0 = dt * 40;
            // load his tile 100x40
            for (int i = tid; i < 100*40; i += 256) {
                int h = i / 40, dd = i - h*40;
                his_s[h*41 + dd] = hisB[(size_t)h*(PK*PD) + d0 + dd];
            }
            // load W tile 40 x cwid
            for (int i = tid; i < 40*cwid; i += 256) {
                int dd = i / cwid, e = i - dd*cwid;
                W_s[dd*113 + e] = W_att[((size_t)k*PD + d0 + dd)*PE + e0 + e];
            }
            __syncthreads();

            #pragma unroll 2
            for (int dd = 0; dd < 40; ++dd) {
                float x[7], w[7];
                #pragma unroll
                for (int i = 0; i < 7; ++i) x[i] = his_s[(ty*7 + i)*41 + dd];
                #pragma unroll
                for (int j = 0; j < 7; ++j) w[j] = W_s[dd*113 + tx*7 + j];
                #pragma unroll
                for (int i = 0; i < 7; ++i)
                    #pragma unroll
                    for (int j = 0; j < 7; ++j)
                        acc[i][j] += x[i] * w[j];
            }
            __syncthreads();
        }

        // epilogue: s[h] += sum_e q*tanh(z+b)
        #pragma unroll
        for (int i = 0; i < 7; ++i) {
            int h = ty*7 + i;
            if (h < PH) {
                float p = 0.f;
                #pragma unroll
                for (int j = 0; j < 7; ++j) {
                    int e = e0 + tx*7 + j;
                    if (e < PE)
                        p += q_att[k*PE + e] * tanhf(acc[i][j] + b_att[k*PE + e]);
                }
                atomicAdd(&s_s[h], p);
            }
        }
        __syncthreads();
    }

    // softmax over h
    if (tid < 32) {
        float m = -1e30f;
        for (int h = tid; h < PH; h += 32) m = fmaxf(m, s_s[h]);
        #pragma unroll
        for (int off = 16; off; off >>= 1)
            m = fmaxf(m, __shfl_xor_sync(0xffffffffu, m, off));
        if (tid == 0) { red_s[0] = m; red_s[1] = 0.f; }
    }
    __syncthreads();
    const float mx = red_s[0];
    if (tid < PH) {
        float ex = __expf(s_s[tid] - mx);
        s_s[tid] = ex;
        atomicAdd(&red_s[1], ex);
    }
    __syncthreads();
    const float inv = 1.f / red_s[1];

    // u[d] = inv * sum_h ex[h]*his[h,d]
    for (int d = tid; d < PD; d += 256) {
        float a0 = 0.f, a1 = 0.f;
        #pragma unroll 4
        for (int h = 0; h < PH; h += 2) {
            a0 += s_s[h]   * hisB[(size_t)h*(PK*PD) + d];
            a1 += s_s[h+1] * hisB[(size_t)(h+1)*(PK*PD) + d];
        }
        float u = (a0 + a1) * inv;
        u_s[d] = u;
        u_g[bk*PD + d] = u;
    }
    __syncthreads();

    // uW[e] = b_lin[e] + sum_d u[d]*W_lin[d,e]
    for (int e = tid; e < PE; e += 256) {
        float a0 = b_lin[e], a1 = 0.f, a2 = 0.f, a3 = 0.f;
        #pragma unroll 2
        for (int d = 0; d < PD; d += 4) {
            a0 += u_s[d]   * W_lin[(d)*PE + e];
            a1 += u_s[d+1] * W_lin[(d+1)*PE + e];
            a2 += u_s[d+2] * W_lin[(d+2)*PE + e];
            a3 += u_s[d+3] * W_lin[(d+3)*PE + e];
        }
        uW_g[bk*PE + e] = (a0 + a1) + (a2 + a3);
    }
}

// -----------------------------------------------------------------------------
// Kernel B: one block per 8 consecutive n (all same b). W_lin[400:500] cached in
// shared. Per (n,k): score = u.cdd ; sk = sum_e q_vec*tanh(uW + cwgt@W_lin2);
// softmax over k; write scores and the broadcast u_channel output.
// -----------------------------------------------------------------------------
__device__ __forceinline__ float blockReduceSum(float v, float* scratch) {
    const int lane = threadIdx.x & 31;
    const int wid  = threadIdx.x >> 5;
    #pragma unroll
    for (int off = 16; off; off >>= 1)
        v += __shfl_xor_sync(0xffffffffu, v, off);
    if (lane == 0) scratch[wid] = v;
    __syncthreads();
    if (threadIdx.x == 0) {
        float s = 0.f;
        #pragma unroll
        for (int i = 0; i < 8; ++i) s += scratch[i];
        scratch[32] = s;
    }
    __syncthreads();
    float r = scratch[32];
    __syncthreads();   // scratch safe for reuse
    return r;
}

__global__ __launch_bounds__(256) void kernelB(
    const float* __restrict__ cdd, const float* __restrict__ cwt,
    const float* __restrict__ W_lin, const float* __restrict__ q_vec,
    float* __restrict__ out_scores, float* __restrict__ out_u)
{
    extern __shared__ float sm[];
    float* W2   = sm;                 // 100*200
    float* u_s  = W2 + PCW*PE;        // 4*400
    float* uW_s = u_s + PK*PD;        // 4*200
    float* cw_s = uW_s + PK*PE;       // 100
    float* red  = cw_s + PCW;         // 33
    float* sk_s = red + 33;           // 4
    float* sc_s = sk_s + 4;           // 4

    const int tid = threadIdx.x;
    const int nb  = blockIdx.x;       // handles n in [nb*8, nb*8+8)
    const int b   = nb >> 2;          // 8 n per block, 32 per b

    for (int i = tid; i < PCW*PE; i += 256) W2[i] = W_lin[PD*PE + i];
    for (int i = tid; i < PK*PD; i += 256) u_s[i]  = u_g[b*PK*PD + i];
    for (int i = tid; i < PK*PE; i += 256) uW_s[i] = uW_g[b*PK*PE + i];
    __syncthreads();

    for (int c8 = 0; c8 < 8; ++c8) {
        const int n = nb*8 + c8;

        for (int k = 0; k < PK; ++k) {
            __syncthreads();
            if (tid < PCW) cw_s[tid] = cwt[((size_t)n*PK + k)*PCW + tid];
            __syncthreads();

            // score partial
            float sp = 0.f;
            for (int d = tid; d < PD; d += 256)
                sp += u_s[k*PD + d] * cdd[((size_t)n*PK + k)*PD + d];

            // temp / sk partial
            float pv = 0.f;
            if (tid < PE) {
                float v0 = uW_s[k*PE + tid], v1 = 0.f;
                #pragma unroll 5
                for (int f = 0; f < PCW; f += 2) {
                    v0 += cw_s[f]   * W2[(f)*PE + tid];
                    v1 += cw_s[f+1] * W2[(f+1)*PE + tid];
                }
                pv = tanhf(v0 + v1) * q_vec[tid];
            }

            float r0 = blockReduceSum(sp, red);
            float r1 = blockReduceSum(pv, red);
            if (tid == 0) { sc_s[k] = r0; sk_s[k] = r1; }
        }
        __syncthreads();

        if (tid == 0) {
            float m = fmaxf(fmaxf(sk_s[0], sk_s[1]), fmaxf(sk_s[2], sk_s[3]));
            float w0 = __expf(sk_s[0]-m), w1 = __expf(sk_s[1]-m);
            float w2 = __expf(sk_s[2]-m), w3 = __expf(sk_s[3]-m);
            float s  = w0 + w1 + w2 + w3;
            out_scores[n] = (w0*sc_s[0] + w1*sc_s[1] + w2*sc_s[2] + w3*sc_s[3]) / s;
        }
        // u_channel broadcast write: out_u[n, k, d]
        for (int i = tid; i < PK*PD; i += 256)
            out_u[(size_t)n*(PK*PD) + i] = u_s[i];
    }
}

extern "C" void kernel_launch(void* const* d_in, const int* in_sizes, int n_in,
                              void* d_out, int out_size)
{
    const float* his   = (const float*)d_in[0];
    const float* cdd   = (const float*)d_in[1];
    const float* cwt   = (const float*)d_in[2];
    const float* W_att = (const float*)d_in[3];
    const float* b_att = (const float*)d_in[4];
    const float* q_att = (const float*)d_in[5];
    const float* W_lin = (const float*)d_in[6];
    const float* b_lin = (const float*)d_in[7];
    const float* q_vec = (const float*)d_in[8];
    float* out = (float*)d_out;

    (void)in_sizes; (void)n_in; (void)out_size;

    kernelA<<<PB*PK, 256>>>(his, W_att, b_att, q_att, W_lin, b_lin);

    const int smemB = (PCW*PE + PK*PD + PK*PE + PCW + 33 + 4 + 4) * (int)sizeof(float);
    cudaFuncSetAttribute(kernelB, cudaFuncAttributeMaxDynamicSharedMemorySize, smemB);
    // outputs concatenated in return order: scores [N,1] then u_channel [N,K,D]
    kernelB<<<PN/8, 256, smemB>>>(cdd, cwt, W_lin, q_vec, out, out + PN);
}

// round 2
// speedup vs baseline: 2.4665x; 2.4665x over previous
#include <cuda_runtime.h>
#include <math.h>

// Problem constants
#define PB  128
#define PH  100
#define PC  32
#define PK  4
#define PD  400
#define PE  200
#define PCW 100
#define PN  (PB*PC)

typedef unsigned long long ull;

// Scratch
__device__ __align__(16) float u_g[PB*PK*PD];
__device__ __align__(16) float uW_g[PB*PK*PE];
__device__ __align__(16) float sk_g[PN*PK];

// ---- packed fp32x2 helpers (Blackwell dual-rate FP32 path) ----
__device__ __forceinline__ ull pack2(float a, float b) {
    ull r; asm("mov.b64 %0, {%1, %2};" : "=l"(r) : "f"(a), "f"(b)); return r;
}
__device__ __forceinline__ ull packdup(float a) {
    ull r; asm("mov.b64 %0, {%1, %1};" : "=l"(r) : "f"(a)); return r;
}
__device__ __forceinline__ void unpack2(ull v, float& a, float& b) {
    asm("mov.b64 {%0, %1}, %2;" : "=f"(a), "=f"(b) : "l"(v));
}
__device__ __forceinline__ void fma2(ull& d, ull a, ull b) {
    asm("fma.rn.f32x2 %0, %1, %2, %0;" : "+l"(d) : "l"(a), "l"(b));
}
__device__ __forceinline__ float tanh_fast(float x) {
    return __fdividef(2.f, 1.f + __expf(-2.f * x)) - 1.f;
}

// -----------------------------------------------------------------------------
// Kernel A: one block per (b,k). Full attention for that channel.
//  z[h,e] = his[b,:,k,:] @ W_att[k]   (100 x 200 x 400) with FFMA2,
//  s[h] = sum_e q*tanh(z+b), softmax, u = a@his, uW = b_lin + u@W_lin[0:400].
// 256 threads; GEMM uses 250 (ty 0..9 -> 10 h as 5 pairs; tx 0..24 -> 8 e).
// his tile stored transposed [dd][h] so h-pairs load as one LDS.64 broadcast.
// -----------------------------------------------------------------------------
#define DT 40
#define HSS 102   // his_s row stride (even -> 8B-aligned pairs, stride-6 banks)

__global__ void __launch_bounds__(256, 2) kernelA(
    const float* __restrict__ his,
    const float* __restrict__ W_att, const float* __restrict__ b_att,
    const float* __restrict__ q_att, const float* __restrict__ W_lin,
    const float* __restrict__ b_lin)
{
    extern __shared__ float sm[];
    float* his_s = sm;                    // DT * HSS
    float* W_s   = his_s + DT*HSS;        // DT * PE
    __shared__ float s_s[PH];
    __shared__ float u_s[PD];
    __shared__ float red_s[2];

    const int bk = blockIdx.x;
    const int b  = bk >> 2;
    const int k  = bk & 3;
    const int tid = threadIdx.x;
    const int ty = tid / 25;              // 0..9 valid (10 for tid>=250)
    const int tx = tid - ty*25;           // 0..24
    const bool act = (tid < 250);

    for (int i = tid; i < PH; i += 256) s_s[i] = 0.f;

    const float* hisB = his + ((size_t)b*PH)*(PK*PD) + (size_t)k*PD;
    const float* WB   = W_att + (size_t)k*PD*PE;

    ull acc[5][8];
    #pragma unroll
    for (int i = 0; i < 5; ++i)
        #pragma unroll
        for (int j = 0; j < 8; ++j) acc[i][j] = 0ull;

    for (int dt = 0; dt < PD/DT; ++dt) {
        const int d0 = dt * DT;
        // his tile: read h-major (coalesced), store transposed [dd][h]
        for (int i = tid; i < PH*DT; i += 256) {
            int h = i / DT, dd = i - h*DT;
            his_s[dd*HSS + h] = hisB[(size_t)h*(PK*PD) + d0 + dd];
        }
        // W tile: fully contiguous both sides
        for (int i = tid; i < DT*PE; i += 256)
            W_s[i] = WB[d0*PE + i];
        __syncthreads();

        if (act) {
            #pragma unroll 2
            for (int dd = 0; dd < DT; ++dd) {
                const float* hp = his_s + dd*HSS + ty*10;
                const float* wp = W_s + dd*PE + tx;
                ull x2[5], w2[8];
                #pragma unroll
                for (int i = 0; i < 5; ++i) {
                    float2 v = *(const float2*)(hp + 2*i);
                    x2[i] = pack2(v.x, v.y);
                }
                #pragma unroll
                for (int j = 0; j < 8; ++j) w2[j] = packdup(wp[j*25]);
                #pragma unroll
                for (int i = 0; i < 5; ++i)
                    #pragma unroll
                    for (int j = 0; j < 8; ++j)
                        fma2(acc[i][j], x2[i], w2[j]);
            }
        }
        __syncthreads();
    }

    // epilogue: s[h] += sum_e q*tanh(z + b_att)
    if (act) {
        #pragma unroll
        for (int i = 0; i < 5; ++i) {
            float p0 = 0.f, p1 = 0.f;
            #pragma unroll
            for (int j = 0; j < 8; ++j) {
                const int e = j*25 + tx;
                const float ba = b_att[k*PE + e];
                const float qa = q_att[k*PE + e];
                float z0, z1; unpack2(acc[i][j], z0, z1);
                p0 += qa * tanh_fast(z0 + ba);
                p1 += qa * tanh_fast(z1 + ba);
            }
            atomicAdd(&s_s[ty*10 + 2*i],     p0);
            atomicAdd(&s_s[ty*10 + 2*i + 1], p1);
        }
    }
    __syncthreads();

    // softmax over h
    if (tid < 32) {
        float m = -1e30f;
        for (int h = tid; h < PH; h += 32) m = fmaxf(m, s_s[h]);
        #pragma unroll
        for (int off = 16; off; off >>= 1)
            m = fmaxf(m, __shfl_xor_sync(0xffffffffu, m, off));
        if (tid == 0) { red_s[0] = m; red_s[1] = 0.f; }
    }
    __syncthreads();
    const float mx = red_s[0];
    if (tid < PH) {
        float ex = __expf(s_s[tid] - mx);
        s_s[tid] = ex;
        atomicAdd(&red_s[1], ex);
    }
    __syncthreads();
    const float inv = 1.f / red_s[1];

    // u[d] = inv * sum_h ex[h]*his[h,d]
    for (int d = tid; d < PD; d += 256) {
        float a0 = 0.f, a1 = 0.f;
        #pragma unroll 4
        for (int h = 0; h < PH; h += 2) {
            a0 += s_s[h]   * hisB[(size_t)h*(PK*PD) + d];
            a1 += s_s[h+1] * hisB[(size_t)(h+1)*(PK*PD) + d];
        }
        float u = (a0 + a1) * inv;
        u_s[d] = u;
        u_g[bk*PD + d] = u;
    }
    __syncthreads();

    // uW[e] = b_lin[e] + sum_d u[d]*W_lin[d,e]
    for (int e = tid; e < PE; e += 256) {
        float a0 = b_lin[e], a1 = 0.f, a2 = 0.f, a3 = 0.f;
        #pragma unroll 2
        for (int d = 0; d < PD; d += 4) {
            a0 += u_s[d]   * W_lin[(d)*PE + e];
            a1 += u_s[d+1] * W_lin[(d+1)*PE + e];
            a2 += u_s[d+2] * W_lin[(d+2)*PE + e];
            a3 += u_s[d+3] * W_lin[(d+3)*PE + e];
        }
        uW_g[bk*PE + e] = (a0 + a1) + (a2 + a3);
    }
}

// -----------------------------------------------------------------------------
// Kernel C: sk[n,k] = sum_e q_vec[e]*tanh(uW[b,k,e] + cwt[n,k,:]@W_lin2)
// GEMM M=16384 rows((n,k)), N=200, K=100. Tile 64 rows/block, W2 in smem.
// 256 threads: ty 0..31 -> 2 rows each; tx 0..7 -> e = j*16+tx*2 (12 pairs)
// plus scalar e = 192+tx. FFMA2 inner. Warp-level e-reduction (8 lanes).
// -----------------------------------------------------------------------------
__global__ void __launch_bounds__(256) kernelC(
    const float* __restrict__ cwt, const float* __restrict__ W_lin,
    const float* __restrict__ q_vec)
{
    extern __shared__ float sm[];
    float* W2 = sm;             // 100*200
    float* cw = W2 + PCW*PE;    // 64*100

    const int tid = threadIdx.x;
    const int tx = tid & 7;
    const int ty = tid >> 3;
    const int row0 = blockIdx.x * 64;

    for (int i = tid; i < PCW*PE; i += 256) W2[i] = W_lin[PD*PE + i];
    for (int i = tid; i < 64*PCW; i += 256) cw[i] = cwt[(size_t)row0*PCW + i];
    __syncthreads();

    ull acc2[2][12];
    float accS[2] = {0.f, 0.f};
    #pragma unroll
    for (int r = 0; r < 2; ++r)
        #pragma unroll
        for (int j = 0; j < 12; ++j) acc2[r][j] = 0ull;

    const float* c0p = cw + (ty*2)*PCW;
    const float* c1p = c0p + PCW;

    #pragma unroll 2
    for (int f = 0; f < PCW; ++f) {
        const float c0 = c0p[f], c1 = c1p[f];
        const ull cc0 = packdup(c0), cc1 = packdup(c1);
        const float* wrow = W2 + f*PE + tx*2;
        #pragma unroll
        for (int j = 0; j < 12; ++j) {
            float2 wv = *(const float2*)(wrow + j*16);
            ull w2v = pack2(wv.x, wv.y);
            fma2(acc2[0][j], cc0, w2v);
            fma2(acc2[1][j], cc1, w2v);
        }
        const float wl = W2[f*PE + 192 + tx];
        accS[0] += c0 * wl;
        accS[1] += c1 * wl;
    }

    #pragma unroll
    for (int rr = 0; rr < 2; ++rr) {
        const int g = row0 + ty*2 + rr;
        const int n = g >> 2, k = g & 3, b = n >> 5;
        const float* uWp = uW_g + ((b << 2) + k)*PE;
        float p = 0.f;
        #pragma unroll
        for (int j = 0; j < 12; ++j) {
            const int e = j*16 + tx*2;
            float z0, z1; unpack2(acc2[rr][j], z0, z1);
            p += q_vec[e]     * tanh_fast(z0 + uWp[e]);
            p += q_vec[e + 1] * tanh_fast(z1 + uWp[e + 1]);
        }
        {
            const int e = 192 + tx;
            p += q_vec[e] * tanh_fast(accS[rr] + uWp[e]);
        }
        p += __shfl_xor_sync(0xffffffffu, p, 1);
        p += __shfl_xor_sync(0xffffffffu, p, 2);
        p += __shfl_xor_sync(0xffffffffu, p, 4);
        if (tx == 0) sk_g[g] = p;
    }
}

// -----------------------------------------------------------------------------
// Kernel D: per n — softmax over sk[4], score = sum_k w_k*(u_bk . cdd_nk),
// write scores and the broadcast u_channel (float4 copy).
// -----------------------------------------------------------------------------
__global__ void __launch_bounds__(128) kernelD(
    const float* __restrict__ cdd,
    float* __restrict__ out_scores, float* __restrict__ out_u)
{
    const int n = blockIdx.x;
    const int b = n >> 5;
    const int tid = threadIdx.x;
    const int k = tid >> 5;
    const int lane = tid & 31;
    __shared__ float dot_s[4];

    const float* up = u_g + (size_t)((b << 2) + k)*PD;
    const float* cp = cdd + ((size_t)n*PK + k)*PD;
    float a = 0.f;
    for (int d = lane; d < PD; d += 32) a += up[d] * cp[d];
    #pragma unroll
    for (int off = 16; off; off >>= 1)
        a += __shfl_xor_sync(0xffffffffu, a, off);
    if (lane == 0) dot_s[k] = a;
    __syncthreads();

    if (tid == 0) {
        const float s0 = sk_g[n*4], s1 = sk_g[n*4+1], s2 = sk_g[n*4+2], s3 = sk_g[n*4+3];
        const float m = fmaxf(fmaxf(s0, s1), fmaxf(s2, s3));
        const float w0 = __expf(s0 - m), w1 = __expf(s1 - m);
        const float w2 = __expf(s2 - m), w3 = __expf(s3 - m);
        out_scores[n] = (w0*dot_s[0] + w1*dot_s[1] + w2*dot_s[2] + w3*dot_s[3])
                        / (w0 + w1 + w2 + w3);
    }

    const float4* u4 = (const float4*)(u_g + (size_t)b*PK*PD);
    float4* o4 = (float4*)(out_u + (size_t)n*PK*PD);
    #pragma unroll
    for (int i = tid; i < PK*PD/4; i += 128) o4[i] = u4[i];
}

extern "C" void kernel_launch(void* const* d_in, const int* in_sizes, int n_in,
                              void* d_out, int out_size)
{
    const float* his   = (const float*)d_in[0];
    const float* cdd   = (const float*)d_in[1];
    const float* cwt   = (const float*)d_in[2];
    const float* W_att = (const float*)d_in[3];
    const float* b_att = (const float*)d_in[4];
    const float* q_att = (const float*)d_in[5];
    const float* W_lin = (const float*)d_in[6];
    const float* b_lin = (const float*)d_in[7];
    const float* q_vec = (const float*)d_in[8];
    float* out = (float*)d_out;
    (void)in_sizes; (void)n_in; (void)out_size;

    const int smemA = (DT*HSS + DT*PE) * (int)sizeof(float);
    cudaFuncSetAttribute(kernelA, cudaFuncAttributeMaxDynamicSharedMemorySize, smemA);
    kernelA<<<PB*PK, 256, smemA>>>(his, W_att, b_att, q_att, W_lin, b_lin);

    const int smemC = (PCW*PE + 64*PCW) * (int)sizeof(float);
    cudaFuncSetAttribute(kernelC, cudaFuncAttributeMaxDynamicSharedMemorySize, smemC);
    kernelC<<<(PN*PK)/64, 256, smemC>>>(cwt, W_lin, q_vec);

    kernelD<<<PN, 128>>>(cdd, out, out + PN);
}

// round 3
// speedup vs baseline: 2.8513x; 1.1560x over previous
#include <cuda_runtime.h>
#include <math.h>

// Problem constants
#define PB  128
#define PH  100
#define PC  32
#define PK  4
#define PD  400
#define PE  200
#define PCW 100
#define PN  (PB*PC)

#define DT  40          // d-tile
#define HS  44          // his smem row stride (16B aligned)
#define TILE_FLOATS (PH*HS + DT*PE)   // 4400 + 8000 = 12400

typedef unsigned long long ull;

// Scratch
__device__ __align__(16) float u_g[PB*PK*PD];
__device__ __align__(16) float uW_g[PB*PK*PE];
__device__ __align__(16) float sk_g[PN*PK];

// ---- packed fp32x2 helpers ----
__device__ __forceinline__ ull packdup(float a) {
    ull r; asm("mov.b64 %0, {%1, %1};" : "=l"(r) : "f"(a)); return r;
}
__device__ __forceinline__ ull pack2(float a, float b) {
    ull r; asm("mov.b64 %0, {%1, %2};" : "=l"(r) : "f"(a), "f"(b)); return r;
}
__device__ __forceinline__ void unpack2(ull v, float& a, float& b) {
    asm("mov.b64 {%0, %1}, %2;" : "=f"(a), "=f"(b) : "l"(v));
}
__device__ __forceinline__ void fma2(ull& d, ull a, ull b) {
    asm("fma.rn.f32x2 %0, %1, %2, %0;" : "+l"(d) : "l"(a), "l"(b));
}
__device__ __forceinline__ float tanh_fast(float x) {
    return __fdividef(2.f, 1.f + __expf(-2.f * x)) - 1.f;
}

// ---- cp.async helpers ----
__device__ __forceinline__ unsigned smem_u32(const void* p) {
    return (unsigned)__cvta_generic_to_shared(p);
}
__device__ __forceinline__ void cp16(float* dst, const float* src) {
    asm volatile("cp.async.cg.shared.global [%0], [%1], 16;"
                 :: "r"(smem_u32(dst)), "l"(src));
}
__device__ __forceinline__ void cp_commit() {
    asm volatile("cp.async.commit_group;");
}
template <int N>
__device__ __forceinline__ void cp_wait() {
    asm volatile("cp.async.wait_group %0;" :: "n"(N));
}

// -----------------------------------------------------------------------------
// Kernel A: one block per (b,k).
//  z = his_bk @ W_att_k (100x200x400, FFMA2, cp.async double-buffered tiles)
//  s[h]=sum_e q*tanh(z+b); softmax; u = a@his; uW = b_lin + u@W_lin[0:400]
// 250 active threads: ty=tid/25 (0..9) -> 10 h each; tx=tid%25 -> 4 e-pairs
// (e = 2*(tx + 25j)). acc2[10][4] packed pairs.
// -----------------------------------------------------------------------------
__global__ void __launch_bounds__(256, 2) kernelA(
    const float* __restrict__ his,
    const float* __restrict__ W_att, const float* __restrict__ b_att,
    const float* __restrict__ q_att, const float* __restrict__ W_lin,
    const float* __restrict__ b_lin)
{
    extern __shared__ float sm[];   // 2 * TILE_FLOATS
    __shared__ float s_s[PH];
    __shared__ float u_s[PD];
    __shared__ float red_s[2];

    const int bk = blockIdx.x;
    const int b  = bk >> 2;
    const int k  = bk & 3;
    const int tid = threadIdx.x;
    const int ty = tid / 25;          // 0..9 valid
    const int tx = tid - ty*25;       // 0..24
    const bool act = (tid < 250);

    for (int i = tid; i < PH; i += 256) s_s[i] = 0.f;

    const float* hisB = his + ((size_t)b*PH)*(PK*PD) + (size_t)k*PD;
    const float* WB   = W_att + (size_t)k*PD*PE;

    // tile loader: his rows [h][0..39] into hs[h*HS..], W 40x200 contiguous
    auto load_tile = [&](int buf, int d0) {
        float* hs = sm + buf*TILE_FLOATS;
        float* ws = hs + PH*HS;
        #pragma unroll
        for (int t = 0; t < 4; ++t) {               // 1000 his chunks
            int i = tid + t*256;
            if (i < 1000) {
                int h = i / 10, c = i - h*10;
                cp16(hs + h*HS + c*4, hisB + (size_t)h*(PK*PD) + d0 + c*4);
            }
        }
        const float* wsrc = WB + (size_t)d0*PE;
        #pragma unroll
        for (int t = 0; t < 8; ++t) {               // 2000 W chunks
            int i = tid + t*256;
            if (i < 2000) cp16(ws + i*4, wsrc + i*4);
        }
    };

    ull acc[10][4];
    #pragma unroll
    for (int r = 0; r < 10; ++r)
        #pragma unroll
        for (int j = 0; j < 4; ++j) acc[r][j] = 0ull;

    load_tile(0, 0);
    cp_commit();

    for (int dt = 0; dt < PD/DT; ++dt) {
        if (dt < PD/DT - 1) {
            load_tile((dt+1) & 1, (dt+1)*DT);
            cp_commit();
            cp_wait<1>();
        } else {
            cp_wait<0>();
        }
        __syncthreads();

        if (act) {
            const float* hs = sm + (dt & 1)*TILE_FLOATS;
            const float* ws = hs + PH*HS;
            const float* xbase = hs + ty*10*HS;
            const float* wbase = ws + tx*2;
            #pragma unroll 2
            for (int dd = 0; dd < DT; ++dd) {
                ull wv[4];
                const float* wrow = wbase + dd*PE;
                #pragma unroll
                for (int j = 0; j < 4; ++j)
                    wv[j] = *(const ull*)(wrow + j*50);
                #pragma unroll
                for (int r = 0; r < 10; ++r) {
                    ull xv = packdup(xbase[r*HS + dd]);
                    #pragma unroll
                    for (int j = 0; j < 4; ++j)
                        fma2(acc[r][j], xv, wv[j]);
                }
            }
        }
        __syncthreads();
    }

    // epilogue: s[h] += sum_e q*tanh(z + b_att)
    if (act) {
        float qa[8], ba[8];
        #pragma unroll
        for (int j = 0; j < 4; ++j) {
            const int e = 2*(tx + 25*j);
            qa[2*j]   = q_att[k*PE + e];     qa[2*j+1] = q_att[k*PE + e + 1];
            ba[2*j]   = b_att[k*PE + e];     ba[2*j+1] = b_att[k*PE + e + 1];
        }
        #pragma unroll
        for (int r = 0; r < 10; ++r) {
            float p = 0.f;
            #pragma unroll
            for (int j = 0; j < 4; ++j) {
                float z0, z1; unpack2(acc[r][j], z0, z1);
                p += qa[2*j]   * tanh_fast(z0 + ba[2*j]);
                p += qa[2*j+1] * tanh_fast(z1 + ba[2*j+1]);
            }
            atomicAdd(&s_s[ty*10 + r], p);
        }
    }
    __syncthreads();

    // softmax over h
    if (tid < 32) {
        float m = -1e30f;
        for (int h = tid; h < PH; h += 32) m = fmaxf(m, s_s[h]);
        #pragma unroll
        for (int off = 16; off; off >>= 1)
            m = fmaxf(m, __shfl_xor_sync(0xffffffffu, m, off));
        if (tid == 0) { red_s[0] = m; red_s[1] = 0.f; }
    }
    __syncthreads();
    const float mx = red_s[0];
    if (tid < PH) {
        float ex = __expf(s_s[tid] - mx);
        s_s[tid] = ex;
        atomicAdd(&red_s[1], ex);
    }
    __syncthreads();
    const float inv = 1.f / red_s[1];

    // u[d] = inv * sum_h ex[h]*his[h,d]
    for (int d = tid; d < PD; d += 256) {
        float a0 = 0.f, a1 = 0.f;
        #pragma unroll 4
        for (int h = 0; h < PH; h += 2) {
            a0 += s_s[h]   * hisB[(size_t)h*(PK*PD) + d];
            a1 += s_s[h+1] * hisB[(size_t)(h+1)*(PK*PD) + d];
        }
        float u = (a0 + a1) * inv;
        u_s[d] = u;
        u_g[bk*PD + d] = u;
    }
    __syncthreads();

    // uW[e] = b_lin[e] + sum_d u[d]*W_lin[d,e]
    for (int e = tid; e < PE; e += 256) {
        float a0 = b_lin[e], a1 = 0.f, a2 = 0.f, a3 = 0.f;
        #pragma unroll 2
        for (int d = 0; d < PD; d += 4) {
            a0 += u_s[d]   * W_lin[(d)*PE + e];
            a1 += u_s[d+1] * W_lin[(d+1)*PE + e];
            a2 += u_s[d+2] * W_lin[(d+2)*PE + e];
            a3 += u_s[d+3] * W_lin[(d+3)*PE + e];
        }
        uW_g[bk*PE + e] = (a0 + a1) + (a2 + a3);
    }
}

// -----------------------------------------------------------------------------
// Kernel C: sk[n,k] = sum_e q_vec[e]*tanh(uW[b,k,e] + cwt[n,k,:]@W_lin2)
// -----------------------------------------------------------------------------
__global__ void __launch_bounds__(256) kernelC(
    const float* __restrict__ cwt, const float* __restrict__ W_lin,
    const float* __restrict__ q_vec)
{
    extern __shared__ float sm[];
    float* W2 = sm;             // 100*200
    float* cw = W2 + PCW*PE;    // 64*100

    const int tid = threadIdx.x;
    const int tx = tid & 7;
    const int ty = tid >> 3;
    const int row0 = blockIdx.x * 64;

    for (int i = tid; i < PCW*PE; i += 256) W2[i] = W_lin[PD*PE + i];
    for (int i = tid; i < 64*PCW; i += 256) cw[i] = cwt[(size_t)row0*PCW + i];
    __syncthreads();

    ull acc2[2][12];
    float accS[2] = {0.f, 0.f};
    #pragma unroll
    for (int r = 0; r < 2; ++r)
        #pragma unroll
        for (int j = 0; j < 12; ++j) acc2[r][j] = 0ull;

    const float* c0p = cw + (ty*2)*PCW;
    const float* c1p = c0p + PCW;

    #pragma unroll 2
    for (int f = 0; f < PCW; ++f) {
        const float c0 = c0p[f], c1 = c1p[f];
        const ull cc0 = packdup(c0), cc1 = packdup(c1);
        const float* wrow = W2 + f*PE + tx*2;
        #pragma unroll
        for (int j = 0; j < 12; ++j) {
            ull w2v = *(const ull*)(wrow + j*16);
            fma2(acc2[0][j], cc0, w2v);
            fma2(acc2[1][j], cc1, w2v);
        }
        const float wl = W2[f*PE + 192 + tx];
        accS[0] += c0 * wl;
        accS[1] += c1 * wl;
    }

    #pragma unroll
    for (int rr = 0; rr < 2; ++rr) {
        const int g = row0 + ty*2 + rr;
        const int n = g >> 2, kk = g & 3, b = n >> 5;
        const float* uWp = uW_g + ((b << 2) + kk)*PE;
        float p = 0.f;
        #pragma unroll
        for (int j = 0; j < 12; ++j) {
            const int e = j*16 + tx*2;
            float z0, z1; unpack2(acc2[rr][j], z0, z1);
            p += q_vec[e]     * tanh_fast(z0 + uWp[e]);
            p += q_vec[e + 1] * tanh_fast(z1 + uWp[e + 1]);
        }
        {
            const int e = 192 + tx;
            p += q_vec[e] * tanh_fast(accS[rr] + uWp[e]);
        }
        p += __shfl_xor_sync(0xffffffffu, p, 1);
        p += __shfl_xor_sync(0xffffffffu, p, 2);
        p += __shfl_xor_sync(0xffffffffu, p, 4);
        if (tx == 0) sk_g[g] = p;
    }
}

// -----------------------------------------------------------------------------
// Kernel D: per n — softmax over sk[4], score, broadcast u_channel copy.
// -----------------------------------------------------------------------------
__global__ void __launch_bounds__(128) kernelD(
    const float* __restrict__ cdd,
    float* __restrict__ out_scores, float* __restrict__ out_u)
{
    const int n = blockIdx.x;
    const int b = n >> 5;
    const int tid = threadIdx.x;
    const int k = tid >> 5;
    const int lane = tid & 31;
    __shared__ float dot_s[4];

    const float* up = u_g + (size_t)((b << 2) + k)*PD;
    const float* cp = cdd + ((size_t)n*PK + k)*PD;
    float a = 0.f;
    for (int d = lane; d < PD; d += 32) a += up[d] * cp[d];
    #pragma unroll
    for (int off = 16; off; off >>= 1)
        a += __shfl_xor_sync(0xffffffffu, a, off);
    if (lane == 0) dot_s[k] = a;
    __syncthreads();

    if (tid == 0) {
        const float s0 = sk_g[n*4], s1 = sk_g[n*4+1], s2 = sk_g[n*4+2], s3 = sk_g[n*4+3];
        const float m = fmaxf(fmaxf(s0, s1), fmaxf(s2, s3));
        const float w0 = __expf(s0 - m), w1 = __expf(s1 - m);
        const float w2 = __expf(s2 - m), w3 = __expf(s3 - m);
        out_scores[n] = (w0*dot_s[0] + w1*dot_s[1] + w2*dot_s[2] + w3*dot_s[3])
                        / (w0 + w1 + w2 + w3);
    }

    const float4* u4 = (const float4*)(u_g + (size_t)b*PK*PD);
    float4* o4 = (float4*)(out_u + (size_t)n*PK*PD);
    #pragma unroll
    for (int i = tid; i < PK*PD/4; i += 128) o4[i] = u4[i];
}

extern "C" void kernel_launch(void* const* d_in, const int* in_sizes, int n_in,
                              void* d_out, int out_size)
{
    const float* his   = (const float*)d_in[0];
    const float* cdd   = (const float*)d_in[1];
    const float* cwt   = (const float*)d_in[2];
    const float* W_att = (const float*)d_in[3];
    const float* b_att = (const float*)d_in[4];
    const float* q_att = (const float*)d_in[5];
    const float* W_lin = (const float*)d_in[6];
    const float* b_lin = (const float*)d_in[7];
    const float* q_vec = (const float*)d_in[8];
    float* out = (float*)d_out;
    (void)in_sizes; (void)n_in; (void)out_size;

    const int smemA = 2 * TILE_FLOATS * (int)sizeof(float);
    cudaFuncSetAttribute(kernelA, cudaFuncAttributeMaxDynamicSharedMemorySize, smemA);
    kernelA<<<PB*PK, 256, smemA>>>(his, W_att, b_att, q_att, W_lin, b_lin);

    const int smemC = (PCW*PE + 64*PCW) * (int)sizeof(float);
    cudaFuncSetAttribute(kernelC, cudaFuncAttributeMaxDynamicSharedMemorySize, smemC);
    kernelC<<<(PN*PK)/64, 256, smemC>>>(cwt, W_lin, q_vec);

    kernelD<<<PN, 128>>>(cdd, out, out + PN);
}